// round 10
// baseline (speedup 1.0000x reference)
#include <cuda_runtime.h>
#include <cstdint>

// Problem constants (from reference): B=32, R=256, T=4096, t uniform grid
#define T_LEN 4096
#define THREADS 256
#define ITEMS 16                  // blocked: thread owns [tid*16, tid*16+16)
#define EPS 1e-8f

__global__ void w2_zero_kernel(float* __restrict__ out) { out[0] = 0.0f; }

// Skew in float2 units: addr2(i) = i + (i>>4).
// Gather (i = 16*lane + c): conflict-free per 16-lane phase (LDS.64).
// Staging (quad 4g..4g+3): addr2(4g+r) = 4g + (g>>2) + r, contiguous,
// conflict-free per half-warp (STS.64).
__device__ __forceinline__ int qaddr2(int i) { return i + (i >> 4); }

__global__ __launch_bounds__(THREADS, 5) void w2_row_kernel(
    const float* __restrict__ traces,
    const float* __restrict__ t,
    const float* __restrict__ q_raw,
    float* __restrict__ out)
{
    const int row = blockIdx.x;
    const float* __restrict__ x = traces + (size_t)row * T_LEN;
    const float* __restrict__ q = q_raw + (size_t)row * T_LEN;

    __shared__ float2 sh_q2[T_LEN + T_LEN / 16];  // (q[i], q[i+1]-q[i]) pair table (~34 KB)
    __shared__ float sh_last[8];           // lane-31 thread's s[15] per warp
    __shared__ float sh_wsum[8];           // per-warp totals
    __shared__ float sh_woff[9];           // exclusive warp offsets; [8] = U total
    __shared__ float sh_red[8];

    const int tid  = threadIdx.x;
    const int lane = tid & 31;
    const int w    = tid >> 5;
    const int base = tid * ITEMS;

    // ---- grid params (uniform t) ----
    const float t0 = __ldg(t);
    const float dt = __ldg(t + 1) - t0;

    // ---- stage (q, dq) pair table into skewed SMEM ----
    {
        const float4* q4 = reinterpret_cast<const float4*>(q);
#pragma unroll
        for (int k = 0; k < T_LEN / 4 / THREADS; k++) {
            int g = tid + k * THREADS;          // float4 index
            float4 v = q4[g];
            // next = q[4g+4]: lane+1's v.x, except lane 31 (cross-warp) -> ldg
            float nx = __shfl_down_sync(0xffffffffu, v.x, 1);
            if (lane == 31)
                nx = (g == T_LEN / 4 - 1) ? v.w : __ldg(q + 4 * g + 4);
            int b = 4 * g + (g >> 2);           // addr2(4g); quad contiguous
            sh_q2[b + 0] = make_float2(v.x, v.y - v.x);
            sh_q2[b + 1] = make_float2(v.y, v.z - v.y);
            sh_q2[b + 2] = make_float2(v.z, v.w - v.z);
            sh_q2[b + 3] = make_float2(v.w, nx - v.w);
        }
    }

    // ---- load x (blocked, float4), square+eps into registers ----
    float s[ITEMS];
    {
        const float4* x4 = reinterpret_cast<const float4*>(x + base);
#pragma unroll
        for (int k = 0; k < ITEMS / 4; k++) {
            float4 v = x4[k];
            s[4 * k + 0] = v.x * v.x + EPS;
            s[4 * k + 1] = v.y * v.y + EPS;
            s[4 * k + 2] = v.z * v.z + EPS;
            s[4 * k + 3] = v.w * v.w + EPS;
        }
    }

    if (lane == 31) sh_last[w] = s[ITEMS - 1];
    __syncthreads();

    // prev_s = s[base-1]; thread 0 seeds -s[0] so that inc_0 = 0 branch-free
    float prev_s = __shfl_up_sync(0xffffffffu, s[ITEMS - 1], 1);
    if (lane == 0) prev_s = (w > 0) ? sh_last[w - 1] : -s[0];

    // ---- dt-free local scan: inc_j = 0.5*(s[j-1]+s[j]); run = thread total ----
    float run = 0.0f;
    {
        float p = prev_s;
#pragma unroll
        for (int k = 0; k < ITEMS; k++) {
            run += 0.5f * (p + s[k]);
            p = s[k];
        }
    }

    // ---- block scan of per-thread totals ----
    float v = run;
#pragma unroll
    for (int o = 1; o < 32; o <<= 1) {
        float u = __shfl_up_sync(0xffffffffu, v, o);
        if (lane >= o) v += u;
    }
    if (lane == 31) sh_wsum[w] = v;
    __syncthreads();
    if (tid == 0) {
        float acc = 0.0f;
#pragma unroll
        for (int i = 0; i < 8; i++) { sh_woff[i] = acc; acc += sh_wsum[i]; }
        sh_woff[8] = acc;                    // U = total (dt-free integral)
    }
    __syncthreads();

    const float U      = sh_woff[8];
    const float invU   = __fdividef(1.0f, U);
    const float scale  = invU * (float)(T_LEN - 1);
    const float offset = sh_woff[w] + (v - run);   // exclusive prefix for this thread

    // ---- loss: recompute running u, fused pair gather, accumulate ----
    float acc = 0.0f;
    float d_first = 0.0f, d_last = 0.0f;
    {
        float p = prev_s;
        float u = offset;
#pragma unroll
        for (int k = 0; k < ITEMS; k++) {
            u += 0.5f * (p + s[k]);
            p = s[k];

            float pos = u * scale;                    // >= 0 by construction
            int   i   = min((int)pos, T_LEN - 2);
            float fr  = pos - (float)i;
            float2 e  = sh_q2[qaddr2(i)];
            float transport = fmaf(fr, e.y, e.x);

            float tj = fmaf((float)(base + k), dt, t0);
            float d  = tj - transport;
            if (k == 0)         d_first = d;
            if (k == ITEMS - 1) d_last  = d;
            acc = fmaf(d * d, s[k], acc);
        }
    }
    // trapz end-point half weights (only j=0 and j=T-1)
    if (tid == 0)           acc -= 0.5f * d_first * d_first * s[0];
    if (tid == THREADS - 1) acc -= 0.5f * d_last  * d_last  * s[ITEMS - 1];
    acc *= invU;   // wt*pdf = s_j/U (dt cancels)

    // ---- block reduce + global atomic ----
#pragma unroll
    for (int o = 16; o > 0; o >>= 1)
        acc += __shfl_xor_sync(0xffffffffu, acc, o);
    if (lane == 0) sh_red[w] = acc;
    __syncthreads();
    if (tid == 0) {
        float ssum = 0.0f;
#pragma unroll
        for (int i = 0; i < 8; i++) ssum += sh_red[i];
        atomicAdd(out, ssum);
    }
}

extern "C" void kernel_launch(void* const* d_in, const int* in_sizes, int n_in,
                              void* d_out, int out_size)
{
    // Inputs (metadata order): traces [B*R*T], t [T], p [T] (uniform [0,1], unused),
    // q_raw [B*R*T]. Output: scalar float loss.
    const float* traces = (const float*)d_in[0];
    const float* t      = (const float*)d_in[1];
    const float* q_raw  = (const float*)d_in[3];
    float* out = (float*)d_out;

    int n_rows = in_sizes[0] / T_LEN;

    w2_zero_kernel<<<1, 1>>>(out);
    w2_row_kernel<<<n_rows, THREADS>>>(traces, t, q_raw, out);
}

// round 11
// speedup vs baseline: 1.1460x; 1.1460x over previous
#include <cuda_runtime.h>
#include <cuda_fp16.h>
#include <cstdint>

// Problem constants (from reference): B=32, R=256, T=4096, t uniform grid
#define T_LEN 4096
#define THREADS 256
#define ITEMS 16                  // blocked: thread owns [tid*16, tid*16+16)
#define EPS 1e-8f

__global__ void w2_zero_kernel(float* __restrict__ out) { out[0] = 0.0f; }

// Skew (4-byte words): addr(i) = i + (i>>5).
// Gather (i = 16*lane + c): bank bijective in lane -> conflict-free LDS.32.
// Staging (quad 4g..4g+3): addr(4g+r) = 4g + (g>>3) + r, contiguous, CF.
__device__ __forceinline__ int raddr(int i) { return i + (i >> 5); }

__global__ __launch_bounds__(THREADS, 5) void w2_row_kernel(
    const float* __restrict__ traces,
    const float* __restrict__ t,
    const float* __restrict__ q_raw,
    float* __restrict__ out)
{
    const int row = blockIdx.x;
    const float* __restrict__ x = traces + (size_t)row * T_LEN;
    const float* __restrict__ q = q_raw + (size_t)row * T_LEN;

    __shared__ __half2 sh_r[T_LEN + T_LEN / 32];  // residual pair table (~16.9 KB)
    __shared__ float sh_last[8];           // lane-31 thread's s[15] per warp
    __shared__ float sh_wsum[8];           // per-warp totals
    __shared__ float sh_woff[9];           // exclusive warp offsets; [8] = U total
    __shared__ float sh_red[8];

    const int tid  = threadIdx.x;
    const int lane = tid & 31;
    const int w    = tid >> 5;
    const int base = tid * ITEMS;

    // ---- grid params (uniform t) ----
    const float t0 = __ldg(t);
    const float dt = __ldg(t + 1) - t0;

    // ---- stage residual pair table: r[i] = q[i] - (t0 + i*dt), half2(r_i, r_{i+1}) ----
    {
        const float4* q4 = reinterpret_cast<const float4*>(q);
#pragma unroll
        for (int k = 0; k < T_LEN / 4 / THREADS; k++) {
            int g = tid + k * THREADS;          // float4 index
            float4 v = q4[g];
            // q[4g+4]: lane+1's v.x; lane 31 crosses warps -> L1-hit ldg
            float nx = __shfl_down_sync(0xffffffffu, v.x, 1);
            if (lane == 31)
                nx = (g == T_LEN / 4 - 1) ? v.w : __ldg(q + 4 * g + 4);
            float tg = fmaf((float)(4 * g), dt, t0);
            float r0 = v.x - tg;
            float r1 = v.y - (tg + dt);
            float r2 = v.z - (tg + 2.0f * dt);
            float r3 = v.w - (tg + 3.0f * dt);
            float r4 = nx  - (tg + 4.0f * dt);
            int a = 4 * g + (g >> 3);           // raddr(4g); quad contiguous
            sh_r[a + 0] = __floats2half2_rn(r0, r1);
            sh_r[a + 1] = __floats2half2_rn(r1, r2);
            sh_r[a + 2] = __floats2half2_rn(r2, r3);
            sh_r[a + 3] = __floats2half2_rn(r3, r4);
        }
    }

    // ---- load x (blocked, float4), square+eps into registers ----
    float s[ITEMS];
    {
        const float4* x4 = reinterpret_cast<const float4*>(x + base);
#pragma unroll
        for (int k = 0; k < ITEMS / 4; k++) {
            float4 v = x4[k];
            s[4 * k + 0] = v.x * v.x + EPS;
            s[4 * k + 1] = v.y * v.y + EPS;
            s[4 * k + 2] = v.z * v.z + EPS;
            s[4 * k + 3] = v.w * v.w + EPS;
        }
    }

    if (lane == 31) sh_last[w] = s[ITEMS - 1];
    __syncthreads();

    // prev_s = s[base-1]; thread 0 seeds -s[0] so that inc_0 = 0 branch-free
    float prev_s = __shfl_up_sync(0xffffffffu, s[ITEMS - 1], 1);
    if (lane == 0) prev_s = (w > 0) ? sh_last[w - 1] : -s[0];

    // ---- dt-free local scan: inc_j = 0.5*(s[j-1]+s[j]); run = thread total ----
    float run = 0.0f;
    {
        float p = prev_s;
#pragma unroll
        for (int k = 0; k < ITEMS; k++) {
            run += 0.5f * (p + s[k]);
            p = s[k];
        }
    }

    // ---- block scan of per-thread totals ----
    float v = run;
#pragma unroll
    for (int o = 1; o < 32; o <<= 1) {
        float u = __shfl_up_sync(0xffffffffu, v, o);
        if (lane >= o) v += u;
    }
    if (lane == 31) sh_wsum[w] = v;
    __syncthreads();
    if (tid == 0) {
        float acc = 0.0f;
#pragma unroll
        for (int i = 0; i < 8; i++) { sh_woff[i] = acc; acc += sh_wsum[i]; }
        sh_woff[8] = acc;                    // U = total (dt-free integral)
    }
    __syncthreads();

    const float U      = sh_woff[8];
    const float invU   = __fdividef(1.0f, U);
    const float scale  = invU * (float)(T_LEN - 1);
    const float offset = sh_woff[w] + (v - run);   // exclusive prefix for this thread

    // ---- loss: running u, single-LDS residual gather, accumulate ----
    float acc = 0.0f;
    float d_first = 0.0f, d_last = 0.0f;
    {
        float p  = prev_s;
        float u  = offset;
        float jf = (float)base;              // exact integers up to 4095
#pragma unroll
        for (int k = 0; k < ITEMS; k++) {
            u += 0.5f * (p + s[k]);
            p = s[k];

            float pos = u * scale;                    // >= 0 by construction
            int   i   = min((int)pos, T_LEN - 2);
            float fr  = pos - (float)i;
            float2 rf = __half22float2(sh_r[raddr(i)]);
            float rint = fmaf(fr, rf.y - rf.x, rf.x);

            // d = (t0 + j*dt) - transport = dt*(j - pos) - rint
            float d = fmaf(dt, jf - pos, -rint);
            if (k == 0)         d_first = d;
            if (k == ITEMS - 1) d_last  = d;
            acc = fmaf(d * d, s[k], acc);
            jf += 1.0f;
        }
    }
    // trapz end-point half weights (only j=0 and j=T-1)
    if (tid == 0)           acc -= 0.5f * d_first * d_first * s[0];
    if (tid == THREADS - 1) acc -= 0.5f * d_last  * d_last  * s[ITEMS - 1];
    acc *= invU;   // wt*pdf = s_j/U (dt cancels)

    // ---- block reduce + global atomic ----
#pragma unroll
    for (int o = 16; o > 0; o >>= 1)
        acc += __shfl_xor_sync(0xffffffffu, acc, o);
    if (lane == 0) sh_red[w] = acc;
    __syncthreads();
    if (tid == 0) {
        float ssum = 0.0f;
#pragma unroll
        for (int i = 0; i < 8; i++) ssum += sh_red[i];
        atomicAdd(out, ssum);
    }
}

extern "C" void kernel_launch(void* const* d_in, const int* in_sizes, int n_in,
                              void* d_out, int out_size)
{
    // Inputs (metadata order): traces [B*R*T], t [T], p [T] (uniform [0,1], unused),
    // q_raw [B*R*T]. Output: scalar float loss.
    const float* traces = (const float*)d_in[0];
    const float* t      = (const float*)d_in[1];
    const float* q_raw  = (const float*)d_in[3];
    float* out = (float*)d_out;

    int n_rows = in_sizes[0] / T_LEN;

    w2_zero_kernel<<<1, 1>>>(out);
    w2_row_kernel<<<n_rows, THREADS>>>(traces, t, q_raw, out);
}

// round 12
// speedup vs baseline: 1.2009x; 1.0479x over previous
#include <cuda_runtime.h>
#include <cuda_fp16.h>
#include <cstdint>

// Problem constants (from reference): B=32, R=256, T=4096, t uniform grid
#define T_LEN 4096
#define THREADS 256
#define ITEMS 16                  // blocked: thread owns [tid*16, tid*16+16)
#define EPS 1e-8f

__global__ void w2_zero_kernel(float* __restrict__ out) { out[0] = 0.0f; }

// Skew (4-byte words): addr(i) = i + (i>>5).
// Gather (i = 16*lane + c): bank bijective in lane -> conflict-free LDS.32.
// Staging (quad 4g..4g+3): addr(4g+r) = 4g + (g>>3) + r, contiguous, CF.
__device__ __forceinline__ int raddr(int i) { return i + (i >> 5); }

__global__ __launch_bounds__(THREADS, 5) void w2_row_kernel(
    const float* __restrict__ traces,
    const float* __restrict__ t,
    const float* __restrict__ q_raw,
    float* __restrict__ out)
{
    const int row = blockIdx.x;
    const float* __restrict__ x = traces + (size_t)row * T_LEN;
    const float* __restrict__ q = q_raw + (size_t)row * T_LEN;

    __shared__ __half2 sh_r[T_LEN + T_LEN / 32];  // residual pair table (~16.9 KB)
    __shared__ float sh_last[8];           // lane-31 thread's s[15] per warp
    __shared__ float sh_wsum[8];           // per-warp totals
    __shared__ float sh_woff[9];           // exclusive warp offsets; [8] = U total
    __shared__ float sh_red[8];

    const int tid  = threadIdx.x;
    const int lane = tid & 31;
    const int w    = tid >> 5;
    const int base = tid * ITEMS;

    // ---- grid params (uniform t) ----
    const float t0 = __ldg(t);
    const float dt = __ldg(t + 1) - t0;

    // ---- stage residual pair table: r[i] = q[i] - (t0 + i*dt), half2(r_i, r_{i+1}) ----
    {
        const float4* q4 = reinterpret_cast<const float4*>(q);
#pragma unroll
        for (int k = 0; k < T_LEN / 4 / THREADS; k++) {
            int g = tid + k * THREADS;          // float4 index
            float4 v = q4[g];
            // q[4g+4]: lane+1's v.x; lane 31 crosses warps -> L1-hit ldg
            float nx = __shfl_down_sync(0xffffffffu, v.x, 1);
            if (lane == 31)
                nx = (g == T_LEN / 4 - 1) ? v.w : __ldg(q + 4 * g + 4);
            float tg = fmaf((float)(4 * g), dt, t0);
            float r0 = v.x - tg;
            float r1 = v.y - (tg + dt);
            float r2 = v.z - (tg + 2.0f * dt);
            float r3 = v.w - (tg + 3.0f * dt);
            float r4 = nx  - (tg + 4.0f * dt);
            int a = 4 * g + (g >> 3);           // raddr(4g); quad contiguous
            sh_r[a + 0] = __floats2half2_rn(r0, r1);
            sh_r[a + 1] = __floats2half2_rn(r1, r2);
            sh_r[a + 2] = __floats2half2_rn(r2, r3);
            sh_r[a + 3] = __floats2half2_rn(r3, r4);
        }
    }

    // ---- load x (blocked, float4), square+eps into registers ----
    float s[ITEMS];
    {
        const float4* x4 = reinterpret_cast<const float4*>(x + base);
#pragma unroll
        for (int k = 0; k < ITEMS / 4; k++) {
            float4 v = x4[k];
            s[4 * k + 0] = v.x * v.x + EPS;
            s[4 * k + 1] = v.y * v.y + EPS;
            s[4 * k + 2] = v.z * v.z + EPS;
            s[4 * k + 3] = v.w * v.w + EPS;
        }
    }

    if (lane == 31) sh_last[w] = s[ITEMS - 1];
    __syncthreads();

    // prev_s = s[base-1]; thread 0 seeds -s[0] so that inc_0 = 0 branch-free
    float prev_s = __shfl_up_sync(0xffffffffu, s[ITEMS - 1], 1);
    if (lane == 0) prev_s = (w > 0) ? sh_last[w - 1] : -s[0];

    // ---- thread total via pairwise tree (no serial chain) ----
    // run = sum_k 0.5*(s[k-1]+s[k]) = sum(s) + 0.5*(prev_s - s[15])
    float run;
    {
        float a0 = s[0]  + s[1],  a1 = s[2]  + s[3];
        float a2 = s[4]  + s[5],  a3 = s[6]  + s[7];
        float a4 = s[8]  + s[9],  a5 = s[10] + s[11];
        float a6 = s[12] + s[13], a7 = s[14] + s[15];
        float b0 = a0 + a1, b1 = a2 + a3, b2 = a4 + a5, b3 = a6 + a7;
        float tot = (b0 + b1) + (b2 + b3);
        run = fmaf(0.5f, prev_s - s[ITEMS - 1], tot);
    }

    // ---- block scan of per-thread totals ----
    float v = run;
#pragma unroll
    for (int o = 1; o < 32; o <<= 1) {
        float u = __shfl_up_sync(0xffffffffu, v, o);
        if (lane >= o) v += u;
    }
    if (lane == 31) sh_wsum[w] = v;
    __syncthreads();
    if (tid == 0) {
        float acc = 0.0f;
#pragma unroll
        for (int i = 0; i < 8; i++) { sh_woff[i] = acc; acc += sh_wsum[i]; }
        sh_woff[8] = acc;                    // U = total (dt-free integral)
    }
    __syncthreads();

    const float U      = sh_woff[8];
    const float invU   = __fdividef(1.0f, U);
    const float scale  = invU * (float)(T_LEN - 1);
    const float cs     = 0.5f * scale;
    const float offset = sh_woff[w] + (v - run);   // exclusive prefix for this thread

    // ---- loss: track pos directly, single-LDS residual gather ----
    float acc = 0.0f;
    float d_first = 0.0f, d_last = 0.0f;
    {
        float p   = prev_s;
        float pos = offset * scale;
        float jf  = (float)base;             // exact integers up to 4095
#pragma unroll
        for (int k = 0; k < ITEMS; k++) {
            pos = fmaf(cs, p + s[k], pos);   // pos = cdf * 4095, in [0, 4095]
            p = s[k];

            int   i  = (int)pos;             // 0..4095; entry 4095 is valid
            float fr = pos - (float)i;
            float2 rf = __half22float2(sh_r[raddr(i)]);
            float rint = fmaf(fr, rf.y - rf.x, rf.x);

            // d = (t0 + j*dt) - transport = dt*(j - pos) - rint
            float d = fmaf(dt, jf - pos, -rint);
            if (k == 0)         d_first = d;
            if (k == ITEMS - 1) d_last  = d;
            acc = fmaf(d * d, s[k], acc);
            jf += 1.0f;
        }
    }
    // trapz end-point half weights (only j=0 and j=T-1)
    if (tid == 0)           acc -= 0.5f * d_first * d_first * s[0];
    if (tid == THREADS - 1) acc -= 0.5f * d_last  * d_last  * s[ITEMS - 1];
    acc *= invU;   // wt*pdf = s_j/U (dt cancels)

    // ---- block reduce + global atomic ----
#pragma unroll
    for (int o = 16; o > 0; o >>= 1)
        acc += __shfl_xor_sync(0xffffffffu, acc, o);
    if (lane == 0) sh_red[w] = acc;
    __syncthreads();
    if (tid == 0) {
        float ssum = 0.0f;
#pragma unroll
        for (int i = 0; i < 8; i++) ssum += sh_red[i];
        atomicAdd(out, ssum);
    }
}

extern "C" void kernel_launch(void* const* d_in, const int* in_sizes, int n_in,
                              void* d_out, int out_size)
{
    // Inputs (metadata order): traces [B*R*T], t [T], p [T] (uniform [0,1], unused),
    // q_raw [B*R*T]. Output: scalar float loss.
    const float* traces = (const float*)d_in[0];
    const float* t      = (const float*)d_in[1];
    const float* q_raw  = (const float*)d_in[3];
    float* out = (float*)d_out;

    int n_rows = in_sizes[0] / T_LEN;

    w2_zero_kernel<<<1, 1>>>(out);
    w2_row_kernel<<<n_rows, THREADS>>>(traces, t, q_raw, out);
}